// round 1
// baseline (speedup 1.0000x reference)
#include <cuda_runtime.h>
#include <cuda_bf16.h>
#include <math.h>

// ---------------------------------------------------------------------------
// Problem dims (fixed by the dataset)
// ---------------------------------------------------------------------------
#define B_  16
#define T_  1024
#define D_  8704
#define R_  256
#define H_  72
#define TH3 (3 * H_)   // 216
#define TAU 12

// ---------------------------------------------------------------------------
// Scratch (no cudaMalloc allowed -> __device__ globals)
// ---------------------------------------------------------------------------
__device__ float g_xr[B_ * T_ * R_];    // [B*T, R]   16.8 MB
__device__ float g_xp[B_ * T_ * TH3];   // [B*T, 3H]  14.2 MB
__device__ float g_q [B_ * T_];         // [B, T]

// ---------------------------------------------------------------------------
// Generic C[M,N] = A[M,K] * B[N,K]^T + bias[N]
// BM=BN=128, BK=8, 256 threads, 8x8 per-thread tile.
// Requires: M % 128 == 0, K % 8 == 0 (true for both uses). N arbitrary.
// ---------------------------------------------------------------------------
__global__ __launch_bounds__(256, 2)
void gemm_tn_kernel(const float* __restrict__ A,
                    const float* __restrict__ Bm,
                    const float* __restrict__ bias,
                    float* __restrict__ C,
                    int M, int N, int K)
{
    __shared__ float As[8][128];
    __shared__ float Bs[8][128];

    const int tid = threadIdx.x;
    const int m0  = blockIdx.y * 128;
    const int n0  = blockIdx.x * 128;

    const int lr = tid >> 1;          // 0..127 : row within tile
    const int lk = (tid & 1) * 4;     // 0 or 4 : k offset
    const int tx = tid & 15;          // n-thread
    const int ty = tid >> 4;          // m-thread

    float acc[8][8];
    #pragma unroll
    for (int i = 0; i < 8; i++)
        #pragma unroll
        for (int j = 0; j < 8; j++) acc[i][j] = 0.f;

    const float* Aptr = A + (size_t)(m0 + lr) * K + lk;
    const bool bvalid = (n0 + lr) < N;
    const float* Bptr = Bm + (size_t)(bvalid ? (n0 + lr) : 0) * K + lk;

    const int nk = K / 8;

    float4 a  = *(const float4*)Aptr;
    float4 bb = bvalid ? *(const float4*)Bptr : make_float4(0.f, 0.f, 0.f, 0.f);

    for (int kt = 0; kt < nk; kt++) {
        As[lk + 0][lr] = a.x;  As[lk + 1][lr] = a.y;
        As[lk + 2][lr] = a.z;  As[lk + 3][lr] = a.w;
        Bs[lk + 0][lr] = bb.x; Bs[lk + 1][lr] = bb.y;
        Bs[lk + 2][lr] = bb.z; Bs[lk + 3][lr] = bb.w;
        __syncthreads();

        if (kt + 1 < nk) {
            a = *(const float4*)(Aptr + (size_t)(kt + 1) * 8);
            if (bvalid) bb = *(const float4*)(Bptr + (size_t)(kt + 1) * 8);
        }

        #pragma unroll
        for (int k = 0; k < 8; k++) {
            float4 a0 = *(const float4*)&As[k][ty * 8];
            float4 a1 = *(const float4*)&As[k][ty * 8 + 4];
            float4 b0 = *(const float4*)&Bs[k][tx * 8];
            float4 b1 = *(const float4*)&Bs[k][tx * 8 + 4];
            float av[8] = {a0.x, a0.y, a0.z, a0.w, a1.x, a1.y, a1.z, a1.w};
            float bv[8] = {b0.x, b0.y, b0.z, b0.w, b1.x, b1.y, b1.z, b1.w};
            #pragma unroll
            for (int i = 0; i < 8; i++)
                #pragma unroll
                for (int j = 0; j < 8; j++)
                    acc[i][j] = fmaf(av[i], bv[j], acc[i][j]);
        }
        __syncthreads();
    }

    #pragma unroll
    for (int i = 0; i < 8; i++) {
        const int m = m0 + ty * 8 + i;
        #pragma unroll
        for (int j = 0; j < 8; j++) {
            const int n = n0 + tx * 8 + j;
            if (n < N) C[(size_t)m * N + n] = acc[i][j] + bias[n];
        }
    }
}

// ---------------------------------------------------------------------------
// GRU: one block per batch element. 224 threads (216 active).
// Thread j owns row j of w_hh (72 regs). h broadcast through SMEM.
//   hp_j = b_hh[j] + dot(w_hh[j,:], h)
//   r = sig(xv+hp), z = sig(xv+hp), n = tanh(xn + r*hn)
//   h = (1-z)*n + z*h;   q[t] = dot(h, w_reg) + b_reg
// ---------------------------------------------------------------------------
__global__ __launch_bounds__(224, 1)
void gru_kernel(const float* __restrict__ xp,
                const float* __restrict__ w_hh,
                const float* __restrict__ b_hh,
                const float* __restrict__ w_reg,
                const float* __restrict__ b_reg,
                float* __restrict__ q)
{
    const int b = blockIdx.x;
    const int j = threadIdx.x;

    __shared__ __align__(16) float h[H_];
    __shared__ float hp[TH3];
    __shared__ float xv[TH3];
    __shared__ float sq;

    float w[H_];
    float bh = 0.f, wr = 0.f;
    if (j < TH3) {
        #pragma unroll
        for (int i = 0; i < H_; i++) w[i] = w_hh[j * H_ + i];
        bh = b_hh[j];
    }
    if (j < H_) { wr = w_reg[j]; h[j] = 0.f; }
    if (j == 0) sq = 0.f;

    const float* xprow = xp + (size_t)b * T_ * TH3;
    const float breg = b_reg[0];
    float xpv = (j < TH3) ? xprow[j] : 0.f;
    __syncthreads();

    for (int t = 0; t < T_; t++) {
        if (j < TH3) {
            float acc = bh;
            #pragma unroll
            for (int i = 0; i < H_; i += 4) {
                float4 h4 = *(const float4*)&h[i];
                acc = fmaf(w[i + 0], h4.x, acc);
                acc = fmaf(w[i + 1], h4.y, acc);
                acc = fmaf(w[i + 2], h4.z, acc);
                acc = fmaf(w[i + 3], h4.w, acc);
            }
            hp[j] = acc;
            xv[j] = xpv;
        }
        // prefetch next step's xp while this step finishes
        float xnext = 0.f;
        if (j < TH3 && t + 1 < T_) xnext = xprow[(size_t)(t + 1) * TH3 + j];
        __syncthreads();

        if (j < H_) {
            float r  = __fdividef(1.f, 1.f + __expf(-(xv[j]        + hp[j])));
            float z  = __fdividef(1.f, 1.f + __expf(-(xv[j + H_]   + hp[j + H_])));
            float n  = tanhf(xv[j + 2 * H_] + r * hp[j + 2 * H_]);
            float hn = (1.f - z) * n + z * h[j];
            h[j] = hn;
            atomicAdd(&sq, hn * wr);
        }
        __syncthreads();

        if (j == 0) { q[b * T_ + t] = sq + breg; sq = 0.f; }
        xpv = xnext;
    }
}

// ---------------------------------------------------------------------------
// sitp + sigmoid heads. One block (1024 threads) per batch element.
// ---------------------------------------------------------------------------
__global__ __launch_bounds__(1024, 1)
void sitp_kernel(const float* __restrict__ q,
                 const int*   __restrict__ xlen,
                 const float* __restrict__ nlm_w1, const float* __restrict__ nlm_b1,
                 const float* __restrict__ nlm_w2, const float* __restrict__ nlm_b2,
                 const float* __restrict__ lm_w,   const float* __restrict__ lm_b,
                 float* __restrict__ out)
{
    const int b = blockIdx.x;
    const int t = threadIdx.x;

    __shared__ float qs[T_];
    __shared__ float ws[T_];
    __shared__ float wqs[T_];
    __shared__ float warpsum[32];

    const int len = xlen[b];
    const float qv = q[b * T_ + t];
    const bool valid = t < len;

    qs[t] = qv;
    const float wv = valid ? expf(-qv) : 0.f;
    ws[t]  = wv;
    wqs[t] = wv * qv;
    __syncthreads();

    float c = 0.f;
    if (valid) {
        // trailing min over [t-TAU+1, t]; all in-window indices are valid (< len)
        float xmin = qv;
        #pragma unroll
        for (int d = 1; d < TAU; d++) {
            int s = t - d;
            if (s >= 0) xmin = fminf(xmin, qs[s]);
        }
        // forward exp(-q)-weighted mean over [t, t+TAU-1]
        float num = 0.f, den = 0.f;
        #pragma unroll
        for (int d = 0; d < TAU; d++) {
            int s = t + d;
            if (s < T_) { num += wqs[s]; den += ws[s]; }
        }
        float y = (den > 0.f) ? num / fmaxf(den, 1e-30f) : 0.f;
        c = 0.5f * y + 0.5f * xmin;   // GAMMA = 0.5
    }

    // block reduction of c over 1024 threads
    #pragma unroll
    for (int off = 16; off > 0; off >>= 1)
        c += __shfl_down_sync(0xFFFFFFFFu, c, off);
    const int wid  = t >> 5;
    const int lane = t & 31;
    if (lane == 0) warpsum[wid] = c;
    __syncthreads();
    if (wid == 0) {
        float v = warpsum[lane];
        #pragma unroll
        for (int off = 16; off > 0; off >>= 1)
            v += __shfl_down_sync(0xFFFFFFFFu, v, off);
        if (lane == 0) {
            const float s        = v / (float)len;
            const float relative = 1.f / (1.f + expf(-s));
            const float mapped   = (1.f / (1.f + expf(-(nlm_w1[0] * relative + nlm_b1[0]))))
                                   * nlm_w2[0] + nlm_b2[0];
            const float aligned  = lm_w[0] * mapped + lm_b[0];
            out[b]          = relative;
            out[B_ + b]     = mapped;
            out[2 * B_ + b] = aligned;
        }
    }
}

// ---------------------------------------------------------------------------
// Launch: x, x_len, w_dr, b_dr, w_ih, w_hh, b_ih, b_hh, w_reg, b_reg,
//         nlm_w1, nlm_b1, nlm_w2, nlm_b2, lm_w, lm_b
// ---------------------------------------------------------------------------
extern "C" void kernel_launch(void* const* d_in, const int* in_sizes, int n_in,
                              void* d_out, int out_size)
{
    const float* x     = (const float*)d_in[0];
    const int*   x_len = (const int*)  d_in[1];
    const float* w_dr  = (const float*)d_in[2];
    const float* b_dr  = (const float*)d_in[3];
    const float* w_ih  = (const float*)d_in[4];
    const float* w_hh  = (const float*)d_in[5];
    const float* b_ih  = (const float*)d_in[6];
    const float* b_hh  = (const float*)d_in[7];
    const float* w_reg = (const float*)d_in[8];
    const float* b_reg = (const float*)d_in[9];
    const float* nlm_w1 = (const float*)d_in[10];
    const float* nlm_b1 = (const float*)d_in[11];
    const float* nlm_w2 = (const float*)d_in[12];
    const float* nlm_b2 = (const float*)d_in[13];
    const float* lm_w   = (const float*)d_in[14];
    const float* lm_b   = (const float*)d_in[15];
    float* out = (float*)d_out;

    float* xr; cudaGetSymbolAddress((void**)&xr, g_xr);
    float* xpp; cudaGetSymbolAddress((void**)&xpp, g_xp);
    float* qq; cudaGetSymbolAddress((void**)&qq, g_q);

    // Stage A: xr[B*T, R] = x[B*T, D] @ w_dr[R, D]^T + b_dr
    {
        dim3 grid((R_ + 127) / 128, (B_ * T_) / 128);
        gemm_tn_kernel<<<grid, 256>>>(x, w_dr, b_dr, xr, B_ * T_, R_, D_);
    }
    // Stage B: xp[B*T, 3H] = xr[B*T, R] @ w_ih[3H, R]^T + b_ih
    {
        dim3 grid((TH3 + 127) / 128, (B_ * T_) / 128);
        gemm_tn_kernel<<<grid, 256>>>(xr, w_ih, b_ih, xpp, B_ * T_, TH3, R_);
    }
    // Stage C: GRU recurrence + q = h @ w_reg^T + b_reg
    gru_kernel<<<B_, 224>>>(xpp, w_hh, b_hh, w_reg, b_reg, qq);
    // Stage D: sitp windows + heads
    sitp_kernel<<<B_, T_>>>(qq, x_len, nlm_w1, nlm_b1, nlm_w2, nlm_b2,
                            lm_w, lm_b, out);
}

// round 5
// speedup vs baseline: 1.3445x; 1.3445x over previous
#include <cuda_runtime.h>
#include <cuda_bf16.h>
#include <math.h>
#include <stdint.h>

// ---------------------------------------------------------------------------
// Problem dims (fixed by the dataset)
// ---------------------------------------------------------------------------
#define B_  16
#define T_  1024
#define D_  8704
#define R_  256
#define H_  72
#define TH3 (3 * H_)   // 216
#define TAU 12
#define BT_ (B_ * T_)

#define KC      64            // K elems per pipeline chunk
#define NCHUNK  (D_ / KC)     // 136
#define STAGE_BYTES 49152     // A bf16 128x64 (16KB) + B bf16 256x64 (32KB)
#define DYN_SMEM (2 * STAGE_BYTES + 1024)

// ---------------------------------------------------------------------------
// Scratch (no cudaMalloc allowed -> __device__ globals)
// ---------------------------------------------------------------------------
__device__ float g_xr[BT_ * R_];            // [B*T, R]
__device__ float g_xp[BT_ * TH3];           // [B*T, 3H]
__device__ float g_q [BT_];                 // [B, T]
__device__ __nv_bfloat16 g_wbf[R_ * D_];    // w_dr in bf16

// ---------------------------------------------------------------------------
// Helpers
// ---------------------------------------------------------------------------
__device__ __forceinline__ uint32_t smem_u32(const void* p) {
    uint32_t a;
    asm("{ .reg .u64 t; cvta.to.shared.u64 t, %1; cvt.u32.u64 %0, t; }"
        : "=r"(a) : "l"(p));
    return a;
}

#define SWZ(o) ((o) ^ (((o) >> 3) & 0x70))

__device__ __forceinline__ void ldmatrix_x4(uint32_t* r, uint32_t addr) {
    asm volatile("ldmatrix.sync.aligned.m8n8.x4.shared.b16 {%0,%1,%2,%3}, [%4];"
                 : "=r"(r[0]), "=r"(r[1]), "=r"(r[2]), "=r"(r[3]) : "r"(addr));
}

__device__ __forceinline__ void mma_bf16(float* d, const uint32_t* a,
                                         uint32_t b0, uint32_t b1) {
    asm volatile(
        "mma.sync.aligned.m16n8k16.row.col.f32.bf16.bf16.f32 "
        "{%0,%1,%2,%3}, {%4,%5,%6,%7}, {%8,%9}, {%0,%1,%2,%3};"
        : "+f"(d[0]), "+f"(d[1]), "+f"(d[2]), "+f"(d[3])
        : "r"(a[0]), "r"(a[1]), "r"(a[2]), "r"(a[3]), "r"(b0), "r"(b1));
}

// ---------------------------------------------------------------------------
// w_dr [R, D] fp32 -> bf16
// ---------------------------------------------------------------------------
__global__ __launch_bounds__(256)
void conv_wdr_kernel(const float* __restrict__ w,
                     __nv_bfloat16* __restrict__ o) {
    int i = (blockIdx.x * 256 + threadIdx.x) * 4;
    float4 v = *reinterpret_cast<const float4*>(w + i);
    uint32_t p0, p1;
    asm("cvt.rn.bf16x2.f32 %0, %1, %2;" : "=r"(p0) : "f"(v.y), "f"(v.x));
    asm("cvt.rn.bf16x2.f32 %0, %1, %2;" : "=r"(p1) : "f"(v.w), "f"(v.z));
    *reinterpret_cast<uint2*>(reinterpret_cast<char*>(o) + (size_t)i * 2)
        = make_uint2(p0, p1);
}

// ---------------------------------------------------------------------------
// GEMM1 stage loaders
// A: 128 rows x 64 fp32 -> bf16, 2 threads/row (8 x float4 -> 8 x uint2)
// B: 256 rows x 64 bf16 via cp.async, 1 thread/row (8 x 16B)
// Both SW128-swizzled, 128 B per row.
// ---------------------------------------------------------------------------
__device__ __forceinline__ void ldgA(const float* __restrict__ x,
                                     int m0, int kc, int tid, uint2* a) {
    const int r = tid >> 1, h = tid & 1;
    const float4* ap = reinterpret_cast<const float4*>(
                           x + (size_t)(m0 + r) * D_ + kc) + h * 8;
    #pragma unroll
    for (int i = 0; i < 8; i++) {
        float4 v = ap[i];
        uint32_t p0, p1;
        asm("cvt.rn.bf16x2.f32 %0, %1, %2;" : "=r"(p0) : "f"(v.y), "f"(v.x));
        asm("cvt.rn.bf16x2.f32 %0, %1, %2;" : "=r"(p1) : "f"(v.w), "f"(v.z));
        a[i] = make_uint2(p0, p1);
    }
}

__device__ __forceinline__ void stsA(char* pS, int tid, const uint2* a) {
    const int r = tid >> 1, h = tid & 1;
    const uint32_t ob = r * 128 + h * 64;
    #pragma unroll
    for (int i = 0; i < 8; i++)
        *reinterpret_cast<uint2*>(pS + SWZ(ob + i * 8)) = a[i];
}

__device__ __forceinline__ void cpB(uint32_t dstB,
                                    const __nv_bfloat16* __restrict__ wbf,
                                    int kc, int tid) {
    const __nv_bfloat16* src = wbf + (size_t)tid * D_ + kc;
    const uint32_t ob = tid * 128;
    #pragma unroll
    for (int i = 0; i < 8; i++) {
        uint32_t d = dstB + SWZ(ob + i * 16);
        asm volatile("cp.async.cg.shared.global [%0], [%1], 16;"
                     :: "r"(d), "l"(src + i * 8) : "memory");
    }
}

// ---------------------------------------------------------------------------
// GEMM1: C[16384,256] = x[16384,8704] @ w_dr^T + b_dr  (bf16 mma.sync)
// 128 CTAs, 256 threads (8 warps as 2x4), warp tile 64x64.
// ---------------------------------------------------------------------------
__global__ __launch_bounds__(256, 1)
void gemm1_mma_kernel(const float* __restrict__ x,
                      const float* __restrict__ b_dr,
                      const __nv_bfloat16* __restrict__ wbf,
                      float* __restrict__ C) {
    extern __shared__ char dynsmem[];
    __shared__ float s_bias[R_];

    const int tid  = threadIdx.x;
    const int lane = tid & 31;
    const int wid  = tid >> 5;
    const int wm   = (wid & 1) * 64;   // warp m offset in CTA tile
    const int wn   = (wid >> 1) * 64;  // warp n offset
    const int m0   = blockIdx.x * 128;

    // 1024-align dynamic smem (swizzle assumes aligned base)
    uint32_t raw  = smem_u32(dynsmem);
    uint32_t base = (raw + 1023u) & ~1023u;
    char* sp = dynsmem + (base - raw);

    s_bias[tid] = b_dr[tid];

    float acc[4][8][4];
    #pragma unroll
    for (int i = 0; i < 4; i++)
        #pragma unroll
        for (int j = 0; j < 8; j++)
            #pragma unroll
            for (int k = 0; k < 4; k++) acc[i][j][k] = 0.f;

    uint2 areg[8];

    // Prologue: chunk 0 -> stage 0
    cpB(base + 16384, wbf, 0, tid);
    asm volatile("cp.async.commit_group;" ::: "memory");
    ldgA(x, m0, 0, tid, areg);
    stsA(sp, tid, areg);
    asm volatile("cp.async.wait_group 0;" ::: "memory");
    __syncthreads();

    // ldmatrix lane-address components (constant across chunks)
    const uint32_t aRow = wm + (lane & 15);            // + mi*16
    const uint32_t aColB = (lane >> 4) * 16;           // + ks*32
    const uint32_t bN   = wn + ((lane >> 4) << 3) + (lane & 7); // + nj*16
    const uint32_t bKB  = ((lane >> 3) & 1) * 16;      // + ks*32

    for (int c = 0; c < NCHUNK; c++) {
        const int s = c & 1;
        const uint32_t stage = base + s * STAGE_BYTES;

        if (c + 1 < NCHUNK) {
            cpB(base + (s ^ 1) * STAGE_BYTES + 16384, wbf, (c + 1) * KC, tid);
            asm volatile("cp.async.commit_group;" ::: "memory");
            ldgA(x, m0, (c + 1) * KC, tid, areg);
        }

        #pragma unroll
        for (int ks = 0; ks < 4; ks++) {
            uint32_t af[4][4], bfr[4][4];
            #pragma unroll
            for (int mi = 0; mi < 4; mi++) {
                uint32_t off = (aRow + mi * 16) * 128 + ks * 32 + aColB;
                ldmatrix_x4(af[mi], stage + SWZ(off));
            }
            #pragma unroll
            for (int nj = 0; nj < 4; nj++) {
                uint32_t off = (bN + nj * 16) * 128 + ks * 32 + bKB;
                ldmatrix_x4(bfr[nj], stage + 16384 + SWZ(off));
            }
            #pragma unroll
            for (int mi = 0; mi < 4; mi++)
                #pragma unroll
                for (int nb = 0; nb < 8; nb++)
                    mma_bf16(acc[mi][nb], af[mi],
                             bfr[nb >> 1][(nb & 1) * 2],
                             bfr[nb >> 1][(nb & 1) * 2 + 1]);
        }

        if (c + 1 < NCHUNK) {
            stsA(sp + (s ^ 1) * STAGE_BYTES, tid, areg);
            asm volatile("cp.async.wait_group 0;" ::: "memory");
        }
        __syncthreads();
    }

    // Epilogue: acc -> C (+bias)
    const int erow = lane >> 2;
    const int ecol = (lane & 3) * 2;
    #pragma unroll
    for (int mi = 0; mi < 4; mi++) {
        #pragma unroll
        for (int nb = 0; nb < 8; nb++) {
            const int col = wn + nb * 8 + ecol;
            const float bx = s_bias[col], by = s_bias[col + 1];
            const int r0 = m0 + wm + mi * 16 + erow;
            float2* p0 = reinterpret_cast<float2*>(C + (size_t)r0 * R_ + col);
            float2* p1 = reinterpret_cast<float2*>(C + (size_t)(r0 + 8) * R_ + col);
            *p0 = make_float2(acc[mi][nb][0] + bx, acc[mi][nb][1] + by);
            *p1 = make_float2(acc[mi][nb][2] + bx, acc[mi][nb][3] + by);
        }
    }
}

// ---------------------------------------------------------------------------
// FFMA GEMM for stage B (small): C[M,N] = A[M,K] * B[N,K]^T + bias[N]
// ---------------------------------------------------------------------------
__global__ __launch_bounds__(256, 2)
void gemm_tn_kernel(const float* __restrict__ A,
                    const float* __restrict__ Bm,
                    const float* __restrict__ bias,
                    float* __restrict__ C,
                    int M, int N, int K)
{
    __shared__ float As[8][128];
    __shared__ float Bs[8][128];

    const int tid = threadIdx.x;
    const int m0  = blockIdx.y * 128;
    const int n0  = blockIdx.x * 128;

    const int lr = tid >> 1;
    const int lk = (tid & 1) * 4;
    const int tx = tid & 15;
    const int ty = tid >> 4;

    float acc[8][8];
    #pragma unroll
    for (int i = 0; i < 8; i++)
        #pragma unroll
        for (int j = 0; j < 8; j++) acc[i][j] = 0.f;

    const float* Aptr = A + (size_t)(m0 + lr) * K + lk;
    const bool bvalid = (n0 + lr) < N;
    const float* Bptr = Bm + (size_t)(bvalid ? (n0 + lr) : 0) * K + lk;

    const int nk = K / 8;

    float4 a  = *(const float4*)Aptr;
    float4 bb = bvalid ? *(const float4*)Bptr : make_float4(0.f, 0.f, 0.f, 0.f);

    for (int kt = 0; kt < nk; kt++) {
        As[lk + 0][lr] = a.x;  As[lk + 1][lr] = a.y;
        As[lk + 2][lr] = a.z;  As[lk + 3][lr] = a.w;
        Bs[lk + 0][lr] = bb.x; Bs[lk + 1][lr] = bb.y;
        Bs[lk + 2][lr] = bb.z; Bs[lk + 3][lr] = bb.w;
        __syncthreads();

        if (kt + 1 < nk) {
            a = *(const float4*)(Aptr + (size_t)(kt + 1) * 8);
            if (bvalid) bb = *(const float4*)(Bptr + (size_t)(kt + 1) * 8);
        }

        #pragma unroll
        for (int k = 0; k < 8; k++) {
            float4 a0 = *(const float4*)&As[k][ty * 8];
            float4 a1 = *(const float4*)&As[k][ty * 8 + 4];
            float4 b0 = *(const float4*)&Bs[k][tx * 8];
            float4 b1 = *(const float4*)&Bs[k][tx * 8 + 4];
            float av[8] = {a0.x, a0.y, a0.z, a0.w, a1.x, a1.y, a1.z, a1.w};
            float bv[8] = {b0.x, b0.y, b0.z, b0.w, b1.x, b1.y, b1.z, b1.w};
            #pragma unroll
            for (int i = 0; i < 8; i++)
                #pragma unroll
                for (int j = 0; j < 8; j++)
                    acc[i][j] = fmaf(av[i], bv[j], acc[i][j]);
        }
        __syncthreads();
    }

    #pragma unroll
    for (int i = 0; i < 8; i++) {
        const int m = m0 + ty * 8 + i;
        #pragma unroll
        for (int j = 0; j < 8; j++) {
            const int n = n0 + tx * 8 + j;
            if (n < N) C[(size_t)m * N + n] = acc[i][j] + bias[n];
        }
    }
}

// ---------------------------------------------------------------------------
// GRU: one block per batch element
// ---------------------------------------------------------------------------
__global__ __launch_bounds__(224, 1)
void gru_kernel(const float* __restrict__ xp,
                const float* __restrict__ w_hh,
                const float* __restrict__ b_hh,
                const float* __restrict__ w_reg,
                const float* __restrict__ b_reg,
                float* __restrict__ q)
{
    const int b = blockIdx.x;
    const int j = threadIdx.x;

    __shared__ __align__(16) float h[H_];
    __shared__ float hp[TH3];
    __shared__ float xv[TH3];
    __shared__ float sq;

    float w[H_];
    float bh = 0.f, wr = 0.f;
    if (j < TH3) {
        #pragma unroll
        for (int i = 0; i < H_; i++) w[i] = w_hh[j * H_ + i];
        bh = b_hh[j];
    }
    if (j < H_) { wr = w_reg[j]; h[j] = 0.f; }
    if (j == 0) sq = 0.f;

    const float* xprow = xp + (size_t)b * T_ * TH3;
    const float breg = b_reg[0];
    float xpv = (j < TH3) ? xprow[j] : 0.f;
    __syncthreads();

    for (int t = 0; t < T_; t++) {
        if (j < TH3) {
            float acc = bh;
            #pragma unroll
            for (int i = 0; i < H_; i += 4) {
                float4 h4 = *(const float4*)&h[i];
                acc = fmaf(w[i + 0], h4.x, acc);
                acc = fmaf(w[i + 1], h4.y, acc);
                acc = fmaf(w[i + 2], h4.z, acc);
                acc = fmaf(w[i + 3], h4.w, acc);
            }
            hp[j] = acc;
            xv[j] = xpv;
        }
        float xnext = 0.f;
        if (j < TH3 && t + 1 < T_) xnext = xprow[(size_t)(t + 1) * TH3 + j];
        __syncthreads();

        if (j < H_) {
            float r  = __fdividef(1.f, 1.f + __expf(-(xv[j]        + hp[j])));
            float z  = __fdividef(1.f, 1.f + __expf(-(xv[j + H_]   + hp[j + H_])));
            float n  = tanhf(xv[j + 2 * H_] + r * hp[j + 2 * H_]);
            float hn = (1.f - z) * n + z * h[j];
            h[j] = hn;
            atomicAdd(&sq, hn * wr);
        }
        __syncthreads();

        if (j == 0) { q[b * T_ + t] = sq + breg; sq = 0.f; }
        xpv = xnext;
    }
}

// ---------------------------------------------------------------------------
// sitp + sigmoid heads
// ---------------------------------------------------------------------------
__global__ __launch_bounds__(1024, 1)
void sitp_kernel(const float* __restrict__ q,
                 const int*   __restrict__ xlen,
                 const float* __restrict__ nlm_w1, const float* __restrict__ nlm_b1,
                 const float* __restrict__ nlm_w2, const float* __restrict__ nlm_b2,
                 const float* __restrict__ lm_w,   const float* __restrict__ lm_b,
                 float* __restrict__ out)
{
    const int b = blockIdx.x;
    const int t = threadIdx.x;

    __shared__ float qs[T_];
    __shared__ float ws[T_];
    __shared__ float wqs[T_];
    __shared__ float warpsum[32];

    const int len = xlen[b];
    const float qv = q[b * T_ + t];
    const bool valid = t < len;

    qs[t] = qv;
    const float wv = valid ? expf(-qv) : 0.f;
    ws[t]  = wv;
    wqs[t] = wv * qv;
    __syncthreads();

    float c = 0.f;
    if (valid) {
        float xmin = qv;
        #pragma unroll
        for (int d = 1; d < TAU; d++) {
            int s = t - d;
            if (s >= 0) xmin = fminf(xmin, qs[s]);
        }
        float num = 0.f, den = 0.f;
        #pragma unroll
        for (int d = 0; d < TAU; d++) {
            int s = t + d;
            if (s < T_) { num += wqs[s]; den += ws[s]; }
        }
        float y = (den > 0.f) ? num / fmaxf(den, 1e-30f) : 0.f;
        c = 0.5f * y + 0.5f * xmin;
    }

    #pragma unroll
    for (int off = 16; off > 0; off >>= 1)
        c += __shfl_down_sync(0xFFFFFFFFu, c, off);
    const int wid  = t >> 5;
    const int lane = t & 31;
    if (lane == 0) warpsum[wid] = c;
    __syncthreads();
    if (wid == 0) {
        float v = warpsum[lane];
        #pragma unroll
        for (int off = 16; off > 0; off >>= 1)
            v += __shfl_down_sync(0xFFFFFFFFu, v, off);
        if (lane == 0) {
            const float s        = v / (float)len;
            const float relative = 1.f / (1.f + expf(-s));
            const float mapped   = (1.f / (1.f + expf(-(nlm_w1[0] * relative + nlm_b1[0]))))
                                   * nlm_w2[0] + nlm_b2[0];
            const float aligned  = lm_w[0] * mapped + lm_b[0];
            out[b]          = relative;
            out[B_ + b]     = mapped;
            out[2 * B_ + b] = aligned;
        }
    }
}

// ---------------------------------------------------------------------------
// Launch
// ---------------------------------------------------------------------------
extern "C" void kernel_launch(void* const* d_in, const int* in_sizes, int n_in,
                              void* d_out, int out_size)
{
    const float* x     = (const float*)d_in[0];
    const int*   x_len = (const int*)  d_in[1];
    const float* w_dr  = (const float*)d_in[2];
    const float* b_dr  = (const float*)d_in[3];
    const float* w_ih  = (const float*)d_in[4];
    const float* w_hh  = (const float*)d_in[5];
    const float* b_ih  = (const float*)d_in[6];
    const float* b_hh  = (const float*)d_in[7];
    const float* w_reg = (const float*)d_in[8];
    const float* b_reg = (const float*)d_in[9];
    const float* nlm_w1 = (const float*)d_in[10];
    const float* nlm_b1 = (const float*)d_in[11];
    const float* nlm_w2 = (const float*)d_in[12];
    const float* nlm_b2 = (const float*)d_in[13];
    const float* lm_w   = (const float*)d_in[14];
    const float* lm_b   = (const float*)d_in[15];
    float* out = (float*)d_out;

    float* xr;  cudaGetSymbolAddress((void**)&xr,  g_xr);
    float* xpp; cudaGetSymbolAddress((void**)&xpp, g_xp);
    float* qq;  cudaGetSymbolAddress((void**)&qq,  g_q);
    __nv_bfloat16* wbf; cudaGetSymbolAddress((void**)&wbf, g_wbf);

    cudaFuncSetAttribute(gemm1_mma_kernel,
                         cudaFuncAttributeMaxDynamicSharedMemorySize, DYN_SMEM);

    // w_dr -> bf16
    conv_wdr_kernel<<<(R_ * D_) / 1024, 256>>>(w_dr, wbf);

    // Stage A: xr = x @ w_dr^T + b_dr   (bf16 mma.sync)
    gemm1_mma_kernel<<<BT_ / 128, 256, DYN_SMEM>>>(x, b_dr, wbf, xr);

    // Stage B: xp = xr @ w_ih^T + b_ih  (FFMA)
    {
        dim3 grid((TH3 + 127) / 128, BT_ / 128);
        gemm_tn_kernel<<<grid, 256>>>(xr, w_ih, b_ih, xpp, BT_, TH3, R_);
    }
    // Stage C: GRU recurrence + q
    gru_kernel<<<B_, 224>>>(xpp, w_hh, b_hh, w_reg, b_reg, qq);
    // Stage D: sitp windows + heads
    sitp_kernel<<<B_, T_>>>(qq, x_len, nlm_w1, nlm_b1, nlm_w2, nlm_b2,
                            lm_w, lm_b, out);
}

// round 8
// speedup vs baseline: 2.2960x; 1.7077x over previous
#include <cuda_runtime.h>
#include <cuda_bf16.h>
#include <math.h>
#include <stdint.h>

typedef unsigned long long ull;

// ---------------------------------------------------------------------------
// Problem dims (fixed by the dataset)
// ---------------------------------------------------------------------------
#define B_  16
#define T_  1024
#define D_  8704
#define R_  256
#define H_  72
#define TH3 (3 * H_)   // 216
#define TAU 12
#define BT_ (B_ * T_)

// GEMM1 tiling
#define G1_BK   16
#define G1_NCH  (D_ / G1_BK)          // 544
#define G1_STAGE_FLOATS (G1_BK * 128 + G1_BK * 256)   // 6144
#define G1_STAGE_BYTES  (G1_STAGE_FLOATS * 4)         // 24576
#define G1_DYN  (2 * G1_STAGE_BYTES)                  // 49152 = 48KB

// ---------------------------------------------------------------------------
// Scratch (no cudaMalloc allowed -> __device__ globals)
// ---------------------------------------------------------------------------
__device__ float g_xr[BT_ * R_];            // [B*T, R]
__device__ float g_xp[BT_ * TH3];           // [B*T, 3H]
__device__ float g_q [BT_];                 // [B, T]

// ---------------------------------------------------------------------------
// f32x2 packed helpers
// ---------------------------------------------------------------------------
__device__ __forceinline__ uint32_t smem_u32(const void* p) {
    uint32_t a;
    asm("{ .reg .u64 t; cvta.to.shared.u64 t, %1; cvt.u32.u64 %0, t; }"
        : "=r"(a) : "l"(p));
    return a;
}

__device__ __forceinline__ ull ffma2(ull a, ull b, ull c) {
    ull d;
    asm("fma.rn.f32x2 %0, %1, %2, %3;" : "=l"(d) : "l"(a), "l"(b), "l"(c));
    return d;
}

__device__ __forceinline__ ull fadd2(ull a, ull b) {
    ull d;
    asm("add.rn.f32x2 %0, %1, %2;" : "=l"(d) : "l"(a), "l"(b));
    return d;
}

__device__ __forceinline__ ull dupf(float f) {
    ull d;
    asm("mov.b64 %0, {%1, %1};" : "=l"(d) : "r"(__float_as_uint(f)));
    return d;
}

__device__ __forceinline__ ull packf(float lo, float hi) {
    ull d;
    asm("mov.b64 %0, {%1, %2};" : "=l"(d)
        : "r"(__float_as_uint(lo)), "r"(__float_as_uint(hi)));
    return d;
}

__device__ __forceinline__ float f2lo(ull u) {
    return __uint_as_float((uint32_t)u);
}
__device__ __forceinline__ float f2hi(ull u) {
    return __uint_as_float((uint32_t)(u >> 32));
}

// ---------------------------------------------------------------------------
// GEMM1: C[16384,256] = x[16384,8704] @ w_dr[256,8704]^T + b_dr   (f32x2)
// 128 CTAs, 256 threads. Per-thread 16x8 tile (8 row-pairs x 8 cols).
// SMEM: As [BK][128] (m-contiguous -> natural row pairs), Bs [BK][256].
// NOTE: no static __shared__ here — dynamic smem is exactly the 48KB default
// limit; static+dynamic must stay <= 49152 without opt-in.
// ---------------------------------------------------------------------------
__global__ __launch_bounds__(256, 1)
void gemm1_f2_kernel(const float* __restrict__ A,
                     const float* __restrict__ Bw,
                     const float* __restrict__ bias,
                     float* __restrict__ C) {
    extern __shared__ float dsm[];

    const int tid = threadIdx.x;
    const int tc  = tid & 31;     // col group: cols tc*8 .. +8
    const int tr  = tid >> 5;     // row group: rows tr*16 .. +16
    const int m0  = blockIdx.x * 128;

    const uint32_t sbase = smem_u32(dsm);

    ull acc[8][8];
    #pragma unroll
    for (int p = 0; p < 8; p++)
        #pragma unroll
        for (int j = 0; j < 8; j++) acc[p][j] = 0ull;

    // global load addressing
    const int ar = tid >> 1, ah = tid & 1;               // A: row, k-half
    const float* aptr = A + (size_t)(m0 + ar) * D_ + ah * 8;
    const float* bptr = Bw + (size_t)tid * D_;           // B: row n = tid

    float4 areg[2], breg[4];

    // prologue: chunk 0 -> stage 0
    areg[0] = *(const float4*)(aptr + 0);
    areg[1] = *(const float4*)(aptr + 4);
    breg[0] = *(const float4*)(bptr + 0);
    breg[1] = *(const float4*)(bptr + 4);
    breg[2] = *(const float4*)(bptr + 8);
    breg[3] = *(const float4*)(bptr + 12);
    {
        float* As = dsm;                 // stage 0
        float* Bs = dsm + G1_BK * 128;
        const float av[8] = {areg[0].x, areg[0].y, areg[0].z, areg[0].w,
                             areg[1].x, areg[1].y, areg[1].z, areg[1].w};
        #pragma unroll
        for (int i = 0; i < 8; i++) As[(ah * 8 + i) * 128 + ar] = av[i];
        const float bv[16] = {breg[0].x, breg[0].y, breg[0].z, breg[0].w,
                              breg[1].x, breg[1].y, breg[1].z, breg[1].w,
                              breg[2].x, breg[2].y, breg[2].z, breg[2].w,
                              breg[3].x, breg[3].y, breg[3].z, breg[3].w};
        #pragma unroll
        for (int i = 0; i < 16; i++) Bs[i * 256 + tid] = bv[i];
    }
    __syncthreads();

    for (int c = 0; c < G1_NCH; c++) {
        const int s = c & 1;

        if (c + 1 < G1_NCH) {
            const float* ap = aptr + (size_t)(c + 1) * G1_BK;
            const float* bp = bptr + (size_t)(c + 1) * G1_BK;
            areg[0] = *(const float4*)(ap + 0);
            areg[1] = *(const float4*)(ap + 4);
            breg[0] = *(const float4*)(bp + 0);
            breg[1] = *(const float4*)(bp + 4);
            breg[2] = *(const float4*)(bp + 8);
            breg[3] = *(const float4*)(bp + 12);
        }

        // compute on stage s
        {
            const uint32_t sA = sbase + s * G1_STAGE_BYTES + tr * 64;
            const float*  Bs = dsm + s * G1_STAGE_FLOATS + G1_BK * 128 + tc * 8;
            #pragma unroll 4
            for (int k = 0; k < G1_BK; k++) {
                ull a[8];
                const uint32_t ab = sA + k * 512;
                asm("ld.shared.v2.b64 {%0,%1}, [%2];"
                    : "=l"(a[0]), "=l"(a[1]) : "r"(ab));
                asm("ld.shared.v2.b64 {%0,%1}, [%2];"
                    : "=l"(a[2]), "=l"(a[3]) : "r"(ab + 16));
                asm("ld.shared.v2.b64 {%0,%1}, [%2];"
                    : "=l"(a[4]), "=l"(a[5]) : "r"(ab + 32));
                asm("ld.shared.v2.b64 {%0,%1}, [%2];"
                    : "=l"(a[6]), "=l"(a[7]) : "r"(ab + 48));
                const float4 b0 = *(const float4*)(Bs + k * 256);
                const float4 b1 = *(const float4*)(Bs + k * 256 + 4);
                ull bd[8];
                bd[0] = dupf(b0.x); bd[1] = dupf(b0.y);
                bd[2] = dupf(b0.z); bd[3] = dupf(b0.w);
                bd[4] = dupf(b1.x); bd[5] = dupf(b1.y);
                bd[6] = dupf(b1.z); bd[7] = dupf(b1.w);
                #pragma unroll
                for (int p = 0; p < 8; p++)
                    #pragma unroll
                    for (int j = 0; j < 8; j++)
                        acc[p][j] = ffma2(a[p], bd[j], acc[p][j]);
            }
        }

        if (c + 1 < G1_NCH) {
            float* As = dsm + (s ^ 1) * G1_STAGE_FLOATS;
            float* Bs = As + G1_BK * 128;
            const float av[8] = {areg[0].x, areg[0].y, areg[0].z, areg[0].w,
                                 areg[1].x, areg[1].y, areg[1].z, areg[1].w};
            #pragma unroll
            for (int i = 0; i < 8; i++) As[(ah * 8 + i) * 128 + ar] = av[i];
            const float bv[16] = {breg[0].x, breg[0].y, breg[0].z, breg[0].w,
                                  breg[1].x, breg[1].y, breg[1].z, breg[1].w,
                                  breg[2].x, breg[2].y, breg[2].z, breg[2].w,
                                  breg[3].x, breg[3].y, breg[3].z, breg[3].w};
            #pragma unroll
            for (int i = 0; i < 16; i++) Bs[i * 256 + tid] = bv[i];
        }
        __syncthreads();
    }

    // epilogue: bias straight from global (L2-resident, 8 floats/thread)
    const int n0 = tc * 8;
    const float4 bia0 = *(const float4*)(bias + n0);
    const float4 bia1 = *(const float4*)(bias + n0 + 4);
    #pragma unroll
    for (int p = 0; p < 8; p++) {
        const int r0 = m0 + tr * 16 + 2 * p;
        float4 lo0 = make_float4(f2lo(acc[p][0]) + bia0.x, f2lo(acc[p][1]) + bia0.y,
                                 f2lo(acc[p][2]) + bia0.z, f2lo(acc[p][3]) + bia0.w);
        float4 lo1 = make_float4(f2lo(acc[p][4]) + bia1.x, f2lo(acc[p][5]) + bia1.y,
                                 f2lo(acc[p][6]) + bia1.z, f2lo(acc[p][7]) + bia1.w);
        float4 hi0 = make_float4(f2hi(acc[p][0]) + bia0.x, f2hi(acc[p][1]) + bia0.y,
                                 f2hi(acc[p][2]) + bia0.z, f2hi(acc[p][3]) + bia0.w);
        float4 hi1 = make_float4(f2hi(acc[p][4]) + bia1.x, f2hi(acc[p][5]) + bia1.y,
                                 f2hi(acc[p][6]) + bia1.z, f2hi(acc[p][7]) + bia1.w);
        *(float4*)(C + (size_t)r0 * R_ + n0)           = lo0;
        *(float4*)(C + (size_t)r0 * R_ + n0 + 4)       = lo1;
        *(float4*)(C + (size_t)(r0 + 1) * R_ + n0)     = hi0;
        *(float4*)(C + (size_t)(r0 + 1) * R_ + n0 + 4) = hi1;
    }
}

// ---------------------------------------------------------------------------
// FFMA GEMM for stage B (small): C[M,N] = A[M,K] * B[N,K]^T + bias[N]
// ---------------------------------------------------------------------------
__global__ __launch_bounds__(256, 2)
void gemm_tn_kernel(const float* __restrict__ A,
                    const float* __restrict__ Bm,
                    const float* __restrict__ bias,
                    float* __restrict__ C,
                    int M, int N, int K)
{
    __shared__ float As[8][128];
    __shared__ float Bs[8][128];

    const int tid = threadIdx.x;
    const int m0  = blockIdx.y * 128;
    const int n0  = blockIdx.x * 128;

    const int lr = tid >> 1;
    const int lk = (tid & 1) * 4;
    const int tx = tid & 15;
    const int ty = tid >> 4;

    float acc[8][8];
    #pragma unroll
    for (int i = 0; i < 8; i++)
        #pragma unroll
        for (int j = 0; j < 8; j++) acc[i][j] = 0.f;

    const float* Aptr = A + (size_t)(m0 + lr) * K + lk;
    const bool bvalid = (n0 + lr) < N;
    const float* Bptr = Bm + (size_t)(bvalid ? (n0 + lr) : 0) * K + lk;

    const int nk = K / 8;

    float4 a  = *(const float4*)Aptr;
    float4 bb = bvalid ? *(const float4*)Bptr : make_float4(0.f, 0.f, 0.f, 0.f);

    for (int kt = 0; kt < nk; kt++) {
        As[lk + 0][lr] = a.x;  As[lk + 1][lr] = a.y;
        As[lk + 2][lr] = a.z;  As[lk + 3][lr] = a.w;
        Bs[lk + 0][lr] = bb.x; Bs[lk + 1][lr] = bb.y;
        Bs[lk + 2][lr] = bb.z; Bs[lk + 3][lr] = bb.w;
        __syncthreads();

        if (kt + 1 < nk) {
            a = *(const float4*)(Aptr + (size_t)(kt + 1) * 8);
            if (bvalid) bb = *(const float4*)(Bptr + (size_t)(kt + 1) * 8);
        }

        #pragma unroll
        for (int k = 0; k < 8; k++) {
            float4 a0 = *(const float4*)&As[k][ty * 8];
            float4 a1 = *(const float4*)&As[k][ty * 8 + 4];
            float4 b0 = *(const float4*)&Bs[k][tx * 8];
            float4 b1 = *(const float4*)&Bs[k][tx * 8 + 4];
            float av[8] = {a0.x, a0.y, a0.z, a0.w, a1.x, a1.y, a1.z, a1.w};
            float bv[8] = {b0.x, b0.y, b0.z, b0.w, b1.x, b1.y, b1.z, b1.w};
            #pragma unroll
            for (int i = 0; i < 8; i++)
                #pragma unroll
                for (int j = 0; j < 8; j++)
                    acc[i][j] = fmaf(av[i], bv[j], acc[i][j]);
        }
        __syncthreads();
    }

    #pragma unroll
    for (int i = 0; i < 8; i++) {
        const int m = m0 + ty * 8 + i;
        #pragma unroll
        for (int j = 0; j < 8; j++) {
            const int n = n0 + tx * 8 + j;
            if (n < N) C[(size_t)m * N + n] = acc[i][j] + bias[n];
        }
    }
}

// ---------------------------------------------------------------------------
// GRU: one block per batch element, f32x2 matvec.
// ---------------------------------------------------------------------------
__global__ __launch_bounds__(224, 1)
void gru_kernel(const float* __restrict__ xp,
                const float* __restrict__ w_hh,
                const float* __restrict__ b_hh,
                const float* __restrict__ w_reg,
                const float* __restrict__ b_reg,
                float* __restrict__ q)
{
    const int b = blockIdx.x;
    const int j = threadIdx.x;
    const int lane = j & 31;

    __shared__ __align__(16) float h[H_];
    __shared__ float hp[TH3];
    __shared__ float xv[TH3];
    __shared__ float sq;

    ull w2[36];
    ull bh2 = 0ull;
    float wr = 0.f;
    if (j < TH3) {
        #pragma unroll
        for (int i = 0; i < 36; i++)
            w2[i] = packf(w_hh[j * H_ + 2 * i], w_hh[j * H_ + 2 * i + 1]);
        bh2 = packf(b_hh[j], 0.f);
    }
    if (j < H_) { wr = w_reg[j]; h[j] = 0.f; }
    if (j == 0) sq = 0.f;

    const uint32_t hb = smem_u32(h);
    const float* xprow = xp + (size_t)b * T_ * TH3;
    const float breg = b_reg[0];
    float xpv = (j < TH3) ? xprow[j] : 0.f;
    __syncthreads();

    for (int t = 0; t < T_; t++) {
        if (j < TH3) {
            ull a0 = bh2, a1 = 0ull;
            #pragma unroll
            for (int i = 0; i < 18; i++) {
                ull p0, p1;
                asm volatile("ld.shared.v2.b64 {%0,%1}, [%2];"
                             : "=l"(p0), "=l"(p1) : "r"(hb + i * 16));
                a0 = ffma2(w2[2 * i],     p0, a0);
                a1 = ffma2(w2[2 * i + 1], p1, a1);
            }
            ull s = fadd2(a0, a1);
            hp[j] = f2lo(s) + f2hi(s);
            xv[j] = xpv;
        }
        // prefetch next step's xp
        float xnext = 0.f;
        if (j < TH3 && t + 1 < T_) xnext = xprow[(size_t)(t + 1) * TH3 + j];
        __syncthreads();

        float contrib = 0.f;
        if (j < H_) {
            float r  = __fdividef(1.f, 1.f + __expf(-(xv[j]        + hp[j])));
            float z  = __fdividef(1.f, 1.f + __expf(-(xv[j + H_]   + hp[j + H_])));
            float n  = tanhf(xv[j + 2 * H_] + r * hp[j + 2 * H_]);
            float hn = (1.f - z) * n + z * h[j];
            h[j] = hn;
            contrib = hn * wr;
        }
        #pragma unroll
        for (int off = 16; off > 0; off >>= 1)
            contrib += __shfl_down_sync(0xFFFFFFFFu, contrib, off);
        if (lane == 0 && j < 96) atomicAdd(&sq, contrib);
        __syncthreads();

        if (j == 0) { q[b * T_ + t] = sq + breg; sq = 0.f; }
        xpv = xnext;
    }
}

// ---------------------------------------------------------------------------
// sitp + sigmoid heads
// ---------------------------------------------------------------------------
__global__ __launch_bounds__(1024, 1)
void sitp_kernel(const float* __restrict__ q,
                 const int*   __restrict__ xlen,
                 const float* __restrict__ nlm_w1, const float* __restrict__ nlm_b1,
                 const float* __restrict__ nlm_w2, const float* __restrict__ nlm_b2,
                 const float* __restrict__ lm_w,   const float* __restrict__ lm_b,
                 float* __restrict__ out)
{
    const int b = blockIdx.x;
    const int t = threadIdx.x;

    __shared__ float qs[T_];
    __shared__ float ws[T_];
    __shared__ float wqs[T_];
    __shared__ float warpsum[32];

    const int len = xlen[b];
    const float qv = q[b * T_ + t];
    const bool valid = t < len;

    qs[t] = qv;
    const float wv = valid ? expf(-qv) : 0.f;
    ws[t]  = wv;
    wqs[t] = wv * qv;
    __syncthreads();

    float c = 0.f;
    if (valid) {
        float xmin = qv;
        #pragma unroll
        for (int d = 1; d < TAU; d++) {
            int s = t - d;
            if (s >= 0) xmin = fminf(xmin, qs[s]);
        }
        float num = 0.f, den = 0.f;
        #pragma unroll
        for (int d = 0; d < TAU; d++) {
            int s = t + d;
            if (s < T_) { num += wqs[s]; den += ws[s]; }
        }
        float y = (den > 0.f) ? num / fmaxf(den, 1e-30f) : 0.f;
        c = 0.5f * y + 0.5f * xmin;
    }

    #pragma unroll
    for (int off = 16; off > 0; off >>= 1)
        c += __shfl_down_sync(0xFFFFFFFFu, c, off);
    const int wid  = t >> 5;
    const int lane = t & 31;
    if (lane == 0) warpsum[wid] = c;
    __syncthreads();
    if (wid == 0) {
        float v = warpsum[lane];
        #pragma unroll
        for (int off = 16; off > 0; off >>= 1)
            v += __shfl_down_sync(0xFFFFFFFFu, v, off);
        if (lane == 0) {
            const float s        = v / (float)len;
            const float relative = 1.f / (1.f + expf(-s));
            const float mapped   = (1.f / (1.f + expf(-(nlm_w1[0] * relative + nlm_b1[0]))))
                                   * nlm_w2[0] + nlm_b2[0];
            const float aligned  = lm_w[0] * mapped + lm_b[0];
            out[b]          = relative;
            out[B_ + b]     = mapped;
            out[2 * B_ + b] = aligned;
        }
    }
}

// ---------------------------------------------------------------------------
// Launch
// ---------------------------------------------------------------------------
extern "C" void kernel_launch(void* const* d_in, const int* in_sizes, int n_in,
                              void* d_out, int out_size)
{
    const float* x     = (const float*)d_in[0];
    const int*   x_len = (const int*)  d_in[1];
    const float* w_dr  = (const float*)d_in[2];
    const float* b_dr  = (const float*)d_in[3];
    const float* w_ih  = (const float*)d_in[4];
    const float* w_hh  = (const float*)d_in[5];
    const float* b_ih  = (const float*)d_in[6];
    const float* b_hh  = (const float*)d_in[7];
    const float* w_reg = (const float*)d_in[8];
    const float* b_reg = (const float*)d_in[9];
    const float* nlm_w1 = (const float*)d_in[10];
    const float* nlm_b1 = (const float*)d_in[11];
    const float* nlm_w2 = (const float*)d_in[12];
    const float* nlm_b2 = (const float*)d_in[13];
    const float* lm_w   = (const float*)d_in[14];
    const float* lm_b   = (const float*)d_in[15];
    float* out = (float*)d_out;

    float* xr;  cudaGetSymbolAddress((void**)&xr,  g_xr);
    float* xpp; cudaGetSymbolAddress((void**)&xpp, g_xp);
    float* qq;  cudaGetSymbolAddress((void**)&qq,  g_q);

    // Opt in to the full dynamic-smem budget for the big GEMM (static smem
    // removed from that kernel, but keep headroom regardless).
    static bool attr_done = false;
    if (!attr_done) {
        cudaFuncSetAttribute(gemm1_f2_kernel,
                             cudaFuncAttributeMaxDynamicSharedMemorySize, G1_DYN);
        attr_done = true;
    }

    // Stage A: xr = x @ w_dr^T + b_dr   (f32x2, full fp32 precision)
    gemm1_f2_kernel<<<BT_ / 128, 256, G1_DYN>>>(x, w_dr, b_dr, xr);

    // Stage B: xp = xr @ w_ih^T + b_ih  (FFMA)
    {
        dim3 grid((TH3 + 127) / 128, BT_ / 128);
        gemm_tn_kernel<<<grid, 256>>>(xr, w_ih, b_ih, xpp, BT_, TH3, R_);
    }
    // Stage C: GRU recurrence + q
    gru_kernel<<<B_, 224>>>(xpp, w_hh, b_hh, w_reg, b_reg, qq);
    // Stage D: sitp windows + heads
    sitp_kernel<<<B_, T_>>>(qq, x_len, nlm_w1, nlm_b1, nlm_w2, nlm_b2,
                            lm_w, lm_b, out);
}

// round 9
// speedup vs baseline: 2.4483x; 1.0663x over previous
#include <cuda_runtime.h>
#include <cuda_bf16.h>
#include <math.h>
#include <stdint.h>

typedef unsigned long long ull;

// ---------------------------------------------------------------------------
// Problem dims (fixed by the dataset)
// ---------------------------------------------------------------------------
#define B_  16
#define T_  1024
#define D_  8704
#define R_  256
#define H_  72
#define TH3 (3 * H_)   // 216
#define TAU 12
#define BT_ (B_ * T_)

// GEMM1 tiling / unit schedule
#define G1_BK   16
#define KQ_     8                       // k-split factor
#define UCHUNK  (D_ / G1_BK / KQ_)      // 68 chunks per unit
#define NUNITS  (128 * KQ_)             // 1024
#define GRID1   148                     // persistent CTAs (1/SM)
#define G1_STAGE_FLOATS (G1_BK * 128 + G1_BK * 256)   // 6144
#define G1_STAGE_BYTES  (G1_STAGE_FLOATS * 4)         // 24576
#define G1_DYN  (2 * G1_STAGE_BYTES)                  // 49152 = 48KB

// GEMM2
#define G2_NCH  (R_ / G1_BK)            // 16

// ---------------------------------------------------------------------------
// Scratch (no cudaMalloc allowed -> __device__ globals)
// ---------------------------------------------------------------------------
__device__ float g_part[KQ_][BT_ * R_];     // 134MB split-K partials
__device__ float g_xr[BT_ * R_];            // [B*T, R]
__device__ float g_xp[BT_ * TH3];           // [B*T, 3H]
__device__ float g_q [BT_];                 // [B, T]

// ---------------------------------------------------------------------------
// f32x2 packed helpers
// ---------------------------------------------------------------------------
__device__ __forceinline__ uint32_t smem_u32(const void* p) {
    uint32_t a;
    asm("{ .reg .u64 t; cvta.to.shared.u64 t, %1; cvt.u32.u64 %0, t; }"
        : "=r"(a) : "l"(p));
    return a;
}

__device__ __forceinline__ ull ffma2(ull a, ull b, ull c) {
    ull d;
    asm("fma.rn.f32x2 %0, %1, %2, %3;" : "=l"(d) : "l"(a), "l"(b), "l"(c));
    return d;
}

__device__ __forceinline__ ull fadd2(ull a, ull b) {
    ull d;
    asm("add.rn.f32x2 %0, %1, %2;" : "=l"(d) : "l"(a), "l"(b));
    return d;
}

__device__ __forceinline__ ull dupf(float f) {
    ull d;
    asm("mov.b64 %0, {%1, %1};" : "=l"(d) : "r"(__float_as_uint(f)));
    return d;
}

__device__ __forceinline__ ull packf(float lo, float hi) {
    ull d;
    asm("mov.b64 %0, {%1, %2};" : "=l"(d)
        : "r"(__float_as_uint(lo)), "r"(__float_as_uint(hi)));
    return d;
}

__device__ __forceinline__ float f2lo(ull u) {
    return __uint_as_float((uint32_t)u);
}
__device__ __forceinline__ float f2hi(ull u) {
    return __uint_as_float((uint32_t)(u >> 32));
}

__device__ __forceinline__ float tanh_fast(float x) {
    float y;
    asm("tanh.approx.f32 %0, %1;" : "=f"(y) : "f"(x));
    return y;
}

// ---------------------------------------------------------------------------
// GEMM1 (split-K persistent): part[kq][m,n] = x[m, kq-slice] @ w_dr^T
// 148 CTAs, 1024 units (128 m-tiles x 8 k-eighths), static round-robin.
// Per-CTA per unit: BM=128, BN=256, 68 chunks of BK=16.
// ---------------------------------------------------------------------------
__global__ __launch_bounds__(256, 1)
void gemm1_f2_kernel(const float* __restrict__ A,
                     const float* __restrict__ Bw,
                     float* __restrict__ part) {
    extern __shared__ float dsm[];

    const int tid = threadIdx.x;
    const int tc  = tid & 31;     // col group: cols tc*8 .. +8
    const int tr  = tid >> 5;     // row group: rows tr*16 .. +16
    const uint32_t sbase = smem_u32(dsm);

    const int ar = tid >> 1, ah = tid & 1;

    for (int u = blockIdx.x; u < NUNITS; u += GRID1) {
        const int tile = u & 127;
        const int kq   = u >> 7;
        const int m0   = tile * 128;
        const size_t koff = (size_t)kq * (UCHUNK * G1_BK);

        ull acc[8][8];
        #pragma unroll
        for (int p = 0; p < 8; p++)
            #pragma unroll
            for (int j = 0; j < 8; j++) acc[p][j] = 0ull;

        const float* aptr = A + (size_t)(m0 + ar) * D_ + koff + ah * 8;
        const float* bptr = Bw + (size_t)tid * D_ + koff;

        float4 areg[2], breg[4];

        // prologue: chunk 0 -> stage 0
        areg[0] = *(const float4*)(aptr + 0);
        areg[1] = *(const float4*)(aptr + 4);
        breg[0] = *(const float4*)(bptr + 0);
        breg[1] = *(const float4*)(bptr + 4);
        breg[2] = *(const float4*)(bptr + 8);
        breg[3] = *(const float4*)(bptr + 12);
        {
            float* As = dsm;
            float* Bs = dsm + G1_BK * 128;
            const float av[8] = {areg[0].x, areg[0].y, areg[0].z, areg[0].w,
                                 areg[1].x, areg[1].y, areg[1].z, areg[1].w};
            #pragma unroll
            for (int i = 0; i < 8; i++) As[(ah * 8 + i) * 128 + ar] = av[i];
            const float bv[16] = {breg[0].x, breg[0].y, breg[0].z, breg[0].w,
                                  breg[1].x, breg[1].y, breg[1].z, breg[1].w,
                                  breg[2].x, breg[2].y, breg[2].z, breg[2].w,
                                  breg[3].x, breg[3].y, breg[3].z, breg[3].w};
            #pragma unroll
            for (int i = 0; i < 16; i++) Bs[i * 256 + tid] = bv[i];
        }
        __syncthreads();

        for (int c = 0; c < UCHUNK; c++) {
            const int s = c & 1;

            if (c + 1 < UCHUNK) {
                const float* ap = aptr + (size_t)(c + 1) * G1_BK;
                const float* bp = bptr + (size_t)(c + 1) * G1_BK;
                areg[0] = *(const float4*)(ap + 0);
                areg[1] = *(const float4*)(ap + 4);
                breg[0] = *(const float4*)(bp + 0);
                breg[1] = *(const float4*)(bp + 4);
                breg[2] = *(const float4*)(bp + 8);
                breg[3] = *(const float4*)(bp + 12);
            }

            {
                const uint32_t sA = sbase + s * G1_STAGE_BYTES + tr * 64;
                const float*  Bs = dsm + s * G1_STAGE_FLOATS + G1_BK * 128 + tc * 8;
                #pragma unroll 4
                for (int k = 0; k < G1_BK; k++) {
                    ull a[8];
                    const uint32_t ab = sA + k * 512;
                    asm("ld.shared.v2.b64 {%0,%1}, [%2];"
                        : "=l"(a[0]), "=l"(a[1]) : "r"(ab));
                    asm("ld.shared.v2.b64 {%0,%1}, [%2];"
                        : "=l"(a[2]), "=l"(a[3]) : "r"(ab + 16));
                    asm("ld.shared.v2.b64 {%0,%1}, [%2];"
                        : "=l"(a[4]), "=l"(a[5]) : "r"(ab + 32));
                    asm("ld.shared.v2.b64 {%0,%1}, [%2];"
                        : "=l"(a[6]), "=l"(a[7]) : "r"(ab + 48));
                    const float4 b0 = *(const float4*)(Bs + k * 256);
                    const float4 b1 = *(const float4*)(Bs + k * 256 + 4);
                    ull bd[8];
                    bd[0] = dupf(b0.x); bd[1] = dupf(b0.y);
                    bd[2] = dupf(b0.z); bd[3] = dupf(b0.w);
                    bd[4] = dupf(b1.x); bd[5] = dupf(b1.y);
                    bd[6] = dupf(b1.z); bd[7] = dupf(b1.w);
                    #pragma unroll
                    for (int p = 0; p < 8; p++)
                        #pragma unroll
                        for (int j = 0; j < 8; j++)
                            acc[p][j] = ffma2(a[p], bd[j], acc[p][j]);
                }
            }

            if (c + 1 < UCHUNK) {
                float* As = dsm + (s ^ 1) * G1_STAGE_FLOATS;
                float* Bs = As + G1_BK * 128;
                const float av[8] = {areg[0].x, areg[0].y, areg[0].z, areg[0].w,
                                     areg[1].x, areg[1].y, areg[1].z, areg[1].w};
                #pragma unroll
                for (int i = 0; i < 8; i++) As[(ah * 8 + i) * 128 + ar] = av[i];
                const float bv[16] = {breg[0].x, breg[0].y, breg[0].z, breg[0].w,
                                      breg[1].x, breg[1].y, breg[1].z, breg[1].w,
                                      breg[2].x, breg[2].y, breg[2].z, breg[2].w,
                                      breg[3].x, breg[3].y, breg[3].z, breg[3].w};
                #pragma unroll
                for (int i = 0; i < 16; i++) Bs[i * 256 + tid] = bv[i];
            }
            __syncthreads();
        }

        // epilogue: write partial tile (no bias)
        float* Cp = part + (size_t)kq * (BT_ * R_);
        const int n0 = tc * 8;
        #pragma unroll
        for (int p = 0; p < 8; p++) {
            const int r0 = m0 + tr * 16 + 2 * p;
            float4 lo0 = make_float4(f2lo(acc[p][0]), f2lo(acc[p][1]),
                                     f2lo(acc[p][2]), f2lo(acc[p][3]));
            float4 lo1 = make_float4(f2lo(acc[p][4]), f2lo(acc[p][5]),
                                     f2lo(acc[p][6]), f2lo(acc[p][7]));
            float4 hi0 = make_float4(f2hi(acc[p][0]), f2hi(acc[p][1]),
                                     f2hi(acc[p][2]), f2hi(acc[p][3]));
            float4 hi1 = make_float4(f2hi(acc[p][4]), f2hi(acc[p][5]),
                                     f2hi(acc[p][6]), f2hi(acc[p][7]));
            *(float4*)(Cp + (size_t)r0 * R_ + n0)           = lo0;
            *(float4*)(Cp + (size_t)r0 * R_ + n0 + 4)       = lo1;
            *(float4*)(Cp + (size_t)(r0 + 1) * R_ + n0)     = hi0;
            *(float4*)(Cp + (size_t)(r0 + 1) * R_ + n0 + 4) = hi1;
        }
    }
}

// ---------------------------------------------------------------------------
// Reduce 8 split-K partials + bias -> xr. float4-vectorized.
// ---------------------------------------------------------------------------
__global__ __launch_bounds__(256)
void reduce8_kernel(const float* __restrict__ part,
                    const float* __restrict__ bias,
                    float* __restrict__ xr) {
    const int i = blockIdx.x * 256 + threadIdx.x;       // float4 index
    const size_t Q = (size_t)BT_ * R_ / 4;
    const float4* p4 = (const float4*)part;
    float4 s = p4[i];
    #pragma unroll
    for (int q = 1; q < KQ_; q++) {
        float4 v = p4[q * Q + i];
        s.x += v.x; s.y += v.y; s.z += v.z; s.w += v.w;
    }
    const int col4 = i & 63;                             // 64 float4 per row
    const float4 b = *(const float4*)(bias + col4 * 4);
    s.x += b.x; s.y += b.y; s.z += b.z; s.w += b.w;
    ((float4*)xr)[i] = s;
}

// ---------------------------------------------------------------------------
// GEMM2 (f32x2): xp[BT,216] = xr[BT,256] @ w_ih[216,256]^T + b_ih
// 128 CTAs, BM=128, BN=256 (cols >=216 masked), 16 chunks of BK=16.
// ---------------------------------------------------------------------------
__global__ __launch_bounds__(256, 1)
void gemm2_f2_kernel(const float* __restrict__ A,
                     const float* __restrict__ Bw,
                     const float* __restrict__ bias,
                     float* __restrict__ C) {
    extern __shared__ float dsm[];

    const int tid = threadIdx.x;
    const int tc  = tid & 31;
    const int tr  = tid >> 5;
    const int m0  = blockIdx.x * 128;
    const uint32_t sbase = smem_u32(dsm);

    ull acc[8][8];
    #pragma unroll
    for (int p = 0; p < 8; p++)
        #pragma unroll
        for (int j = 0; j < 8; j++) acc[p][j] = 0ull;

    const int ar = tid >> 1, ah = tid & 1;
    const float* aptr = A + (size_t)(m0 + ar) * R_ + ah * 8;
    const bool bval = tid < TH3;
    const float* bptr = Bw + (size_t)(bval ? tid : 0) * R_;

    float4 areg[2], breg[4];
    const float4 z4 = make_float4(0.f, 0.f, 0.f, 0.f);

    areg[0] = *(const float4*)(aptr + 0);
    areg[1] = *(const float4*)(aptr + 4);
    breg[0] = bval ? *(const float4*)(bptr + 0)  : z4;
    breg[1] = bval ? *(const float4*)(bptr + 4)  : z4;
    breg[2] = bval ? *(const float4*)(bptr + 8)  : z4;
    breg[3] = bval ? *(const float4*)(bptr + 12) : z4;
    {
        float* As = dsm;
        float* Bs = dsm + G1_BK * 128;
        const float av[8] = {areg[0].x, areg[0].y, areg[0].z, areg[0].w,
                             areg[1].x, areg[1].y, areg[1].z, areg[1].w};
        #pragma unroll
        for (int i = 0; i < 8; i++) As[(ah * 8 + i) * 128 + ar] = av[i];
        const float bv[16] = {breg[0].x, breg[0].y, breg[0].z, breg[0].w,
                              breg[1].x, breg[1].y, breg[1].z, breg[1].w,
                              breg[2].x, breg[2].y, breg[2].z, breg[2].w,
                              breg[3].x, breg[3].y, breg[3].z, breg[3].w};
        #pragma unroll
        for (int i = 0; i < 16; i++) Bs[i * 256 + tid] = bv[i];
    }
    __syncthreads();

    for (int c = 0; c < G2_NCH; c++) {
        const int s = c & 1;

        if (c + 1 < G2_NCH) {
            const float* ap = aptr + (size_t)(c + 1) * G1_BK;
            const float* bp = bptr + (size_t)(c + 1) * G1_BK;
            areg[0] = *(const float4*)(ap + 0);
            areg[1] = *(const float4*)(ap + 4);
            breg[0] = bval ? *(const float4*)(bp + 0)  : z4;
            breg[1] = bval ? *(const float4*)(bp + 4)  : z4;
            breg[2] = bval ? *(const float4*)(bp + 8)  : z4;
            breg[3] = bval ? *(const float4*)(bp + 12) : z4;
        }

        {
            const uint32_t sA = sbase + s * G1_STAGE_BYTES + tr * 64;
            const float*  Bs = dsm + s * G1_STAGE_FLOATS + G1_BK * 128 + tc * 8;
            #pragma unroll 4
            for (int k = 0; k < G1_BK; k++) {
                ull a[8];
                const uint32_t ab = sA + k * 512;
                asm("ld.shared.v2.b64 {%0,%1}, [%2];"
                    : "=l"(a[0]), "=l"(a[1]) : "r"(ab));
                asm("ld.shared.v2.b64 {%0,%1}, [%2];"
                    : "=l"(a[2]), "=l"(a[3]) : "r"(ab + 16));
                asm("ld.shared.v2.b64 {%0,%1}, [%2];"
                    : "=l"(a[4]), "=l"(a[5]) : "r"(ab + 32));
                asm("ld.shared.v2.b64 {%0,%1}, [%2];"
                    : "=l"(a[6]), "=l"(a[7]) : "r"(ab + 48));
                const float4 b0 = *(const float4*)(Bs + k * 256);
                const float4 b1 = *(const float4*)(Bs + k * 256 + 4);
                ull bd[8];
                bd[0] = dupf(b0.x); bd[1] = dupf(b0.y);
                bd[2] = dupf(b0.z); bd[3] = dupf(b0.w);
                bd[4] = dupf(b1.x); bd[5] = dupf(b1.y);
                bd[6] = dupf(b1.z); bd[7] = dupf(b1.w);
                #pragma unroll
                for (int p = 0; p < 8; p++)
                    #pragma unroll
                    for (int j = 0; j < 8; j++)
                        acc[p][j] = ffma2(a[p], bd[j], acc[p][j]);
            }
        }

        if (c + 1 < G2_NCH) {
            float* As = dsm + (s ^ 1) * G1_STAGE_FLOATS;
            float* Bs = As + G1_BK * 128;
            const float av[8] = {areg[0].x, areg[0].y, areg[0].z, areg[0].w,
                                 areg[1].x, areg[1].y, areg[1].z, areg[1].w};
            #pragma unroll
            for (int i = 0; i < 8; i++) As[(ah * 8 + i) * 128 + ar] = av[i];
            const float bv[16] = {breg[0].x, breg[0].y, breg[0].z, breg[0].w,
                                  breg[1].x, breg[1].y, breg[1].z, breg[1].w,
                                  breg[2].x, breg[2].y, breg[2].z, breg[2].w,
                                  breg[3].x, breg[3].y, breg[3].z, breg[3].w};
            #pragma unroll
            for (int i = 0; i < 16; i++) Bs[i * 256 + tid] = bv[i];
        }
        __syncthreads();
    }

    // epilogue: only cols < 216 exist (tc < 27); row stride TH3 = 216.
    if (tc < 27) {
        const int n0 = tc * 8;
        const float4 bia0 = *(const float4*)(bias + n0);
        const float4 bia1 = *(const float4*)(bias + n0 + 4);
        #pragma unroll
        for (int p = 0; p < 8; p++) {
            const int r0 = m0 + tr * 16 + 2 * p;
            float4 lo0 = make_float4(f2lo(acc[p][0]) + bia0.x, f2lo(acc[p][1]) + bia0.y,
                                     f2lo(acc[p][2]) + bia0.z, f2lo(acc[p][3]) + bia0.w);
            float4 lo1 = make_float4(f2lo(acc[p][4]) + bia1.x, f2lo(acc[p][5]) + bia1.y,
                                     f2lo(acc[p][6]) + bia1.z, f2lo(acc[p][7]) + bia1.w);
            float4 hi0 = make_float4(f2hi(acc[p][0]) + bia0.x, f2hi(acc[p][1]) + bia0.y,
                                     f2hi(acc[p][2]) + bia0.z, f2hi(acc[p][3]) + bia0.w);
            float4 hi1 = make_float4(f2hi(acc[p][4]) + bia1.x, f2hi(acc[p][5]) + bia1.y,
                                     f2hi(acc[p][6]) + bia1.z, f2hi(acc[p][7]) + bia1.w);
            *(float4*)(C + (size_t)r0 * TH3 + n0)           = lo0;
            *(float4*)(C + (size_t)r0 * TH3 + n0 + 4)       = lo1;
            *(float4*)(C + (size_t)(r0 + 1) * TH3 + n0)     = hi0;
            *(float4*)(C + (size_t)(r0 + 1) * TH3 + n0 + 4) = hi1;
        }
    }
}

// ---------------------------------------------------------------------------
// GRU: one block per batch element, f32x2 matvec, tanh.approx.
// ---------------------------------------------------------------------------
__global__ __launch_bounds__(224, 1)
void gru_kernel(const float* __restrict__ xp,
                const float* __restrict__ w_hh,
                const float* __restrict__ b_hh,
                const float* __restrict__ w_reg,
                const float* __restrict__ b_reg,
                float* __restrict__ q)
{
    const int b = blockIdx.x;
    const int j = threadIdx.x;
    const int lane = j & 31;

    __shared__ __align__(16) float h[H_];
    __shared__ float hp[TH3];
    __shared__ float xv[TH3];
    __shared__ float sq;

    ull w2[36];
    ull bh2 = 0ull;
    float wr = 0.f;
    if (j < TH3) {
        #pragma unroll
        for (int i = 0; i < 36; i++)
            w2[i] = packf(w_hh[j * H_ + 2 * i], w_hh[j * H_ + 2 * i + 1]);
        bh2 = packf(b_hh[j], 0.f);
    }
    if (j < H_) { wr = w_reg[j]; h[j] = 0.f; }
    if (j == 0) sq = 0.f;

    const uint32_t hb = smem_u32(h);
    const float* xprow = xp + (size_t)b * T_ * TH3;
    const float breg = b_reg[0];
    float xpv = (j < TH3) ? xprow[j] : 0.f;
    __syncthreads();

    for (int t = 0; t < T_; t++) {
        if (j < TH3) {
            ull a0 = bh2, a1 = 0ull;
            #pragma unroll
            for (int i = 0; i < 18; i++) {
                ull p0, p1;
                asm volatile("ld.shared.v2.b64 {%0,%1}, [%2];"
                             : "=l"(p0), "=l"(p1) : "r"(hb + i * 16));
                a0 = ffma2(w2[2 * i],     p0, a0);
                a1 = ffma2(w2[2 * i + 1], p1, a1);
            }
            ull s = fadd2(a0, a1);
            hp[j] = f2lo(s) + f2hi(s);
            xv[j] = xpv;
        }
        float xnext = 0.f;
        if (j < TH3 && t + 1 < T_) xnext = xprow[(size_t)(t + 1) * TH3 + j];
        __syncthreads();

        float contrib = 0.f;
        if (j < H_) {
            float r  = __fdividef(1.f, 1.f + __expf(-(xv[j]        + hp[j])));
            float z  = __fdividef(1.f, 1.f + __expf(-(xv[j + H_]   + hp[j + H_])));
            float n  = tanh_fast(xv[j + 2 * H_] + r * hp[j + 2 * H_]);
            float hn = (1.f - z) * n + z * h[j];
            h[j] = hn;
            contrib = hn * wr;
        }
        #pragma unroll
        for (int off = 16; off > 0; off >>= 1)
            contrib += __shfl_down_sync(0xFFFFFFFFu, contrib, off);
        if (lane == 0 && j < 96) atomicAdd(&sq, contrib);
        __syncthreads();

        if (j == 0) { q[b * T_ + t] = sq + breg; sq = 0.f; }
        xpv = xnext;
    }
}

// ---------------------------------------------------------------------------
// sitp + sigmoid heads
// ---------------------------------------------------------------------------
__global__ __launch_bounds__(1024, 1)
void sitp_kernel(const float* __restrict__ q,
                 const int*   __restrict__ xlen,
                 const float* __restrict__ nlm_w1, const float* __restrict__ nlm_b1,
                 const float* __restrict__ nlm_w2, const float* __restrict__ nlm_b2,
                 const float* __restrict__ lm_w,   const float* __restrict__ lm_b,
                 float* __restrict__ out)
{
    const int b = blockIdx.x;
    const int t = threadIdx.x;

    __shared__ float qs[T_];
    __shared__ float ws[T_];
    __shared__ float wqs[T_];
    __shared__ float warpsum[32];

    const int len = xlen[b];
    const float qv = q[b * T_ + t];
    const bool valid = t < len;

    qs[t] = qv;
    const float wv = valid ? expf(-qv) : 0.f;
    ws[t]  = wv;
    wqs[t] = wv * qv;
    __syncthreads();

    float c = 0.f;
    if (valid) {
        float xmin = qv;
        #pragma unroll
        for (int d = 1; d < TAU; d++) {
            int s = t - d;
            if (s >= 0) xmin = fminf(xmin, qs[s]);
        }
        float num = 0.f, den = 0.f;
        #pragma unroll
        for (int d = 0; d < TAU; d++) {
            int s = t + d;
            if (s < T_) { num += wqs[s]; den += ws[s]; }
        }
        float y = (den > 0.f) ? num / fmaxf(den, 1e-30f) : 0.f;
        c = 0.5f * y + 0.5f * xmin;
    }

    #pragma unroll
    for (int off = 16; off > 0; off >>= 1)
        c += __shfl_down_sync(0xFFFFFFFFu, c, off);
    const int wid  = t >> 5;
    const int lane = t & 31;
    if (lane == 0) warpsum[wid] = c;
    __syncthreads();
    if (wid == 0) {
        float v = warpsum[lane];
        #pragma unroll
        for (int off = 16; off > 0; off >>= 1)
            v += __shfl_down_sync(0xFFFFFFFFu, v, off);
        if (lane == 0) {
            const float s        = v / (float)len;
            const float relative = 1.f / (1.f + expf(-s));
            const float mapped   = (1.f / (1.f + expf(-(nlm_w1[0] * relative + nlm_b1[0]))))
                                   * nlm_w2[0] + nlm_b2[0];
            const float aligned  = lm_w[0] * mapped + lm_b[0];
            out[b]          = relative;
            out[B_ + b]     = mapped;
            out[2 * B_ + b] = aligned;
        }
    }
}

// ---------------------------------------------------------------------------
// Launch
// ---------------------------------------------------------------------------
extern "C" void kernel_launch(void* const* d_in, const int* in_sizes, int n_in,
                              void* d_out, int out_size)
{
    const float* x     = (const float*)d_in[0];
    const int*   x_len = (const int*)  d_in[1];
    const float* w_dr  = (const float*)d_in[2];
    const float* b_dr  = (const float*)d_in[3];
    const float* w_ih  = (const float*)d_in[4];
    const float* w_hh  = (const float*)d_in[5];
    const float* b_ih  = (const float*)d_in[6];
    const float* b_hh  = (const float*)d_in[7];
    const float* w_reg = (const float*)d_in[8];
    const float* b_reg = (const float*)d_in[9];
    const float* nlm_w1 = (const float*)d_in[10];
    const float* nlm_b1 = (const float*)d_in[11];
    const float* nlm_w2 = (const float*)d_in[12];
    const float* nlm_b2 = (const float*)d_in[13];
    const float* lm_w   = (const float*)d_in[14];
    const float* lm_b   = (const float*)d_in[15];
    float* out = (float*)d_out;

    float* part; cudaGetSymbolAddress((void**)&part, g_part);
    float* xr;   cudaGetSymbolAddress((void**)&xr,   g_xr);
    float* xpp;  cudaGetSymbolAddress((void**)&xpp,  g_xp);
    float* qq;   cudaGetSymbolAddress((void**)&qq,   g_q);

    static bool attr_done = false;
    if (!attr_done) {
        cudaFuncSetAttribute(gemm1_f2_kernel,
                             cudaFuncAttributeMaxDynamicSharedMemorySize, G1_DYN);
        cudaFuncSetAttribute(gemm2_f2_kernel,
                             cudaFuncAttributeMaxDynamicSharedMemorySize, G1_DYN);
        attr_done = true;
    }

    // Stage A: split-K persistent GEMM1 -> 8 partial slabs
    gemm1_f2_kernel<<<GRID1, 256, G1_DYN>>>(x, w_dr, part);
    // Stage A2: reduce partials + bias -> xr
    reduce8_kernel<<<(BT_ * R_ / 4) / 256, 256>>>(part, b_dr, xr);
    // Stage B: xp = xr @ w_ih^T + b_ih  (f32x2)
    gemm2_f2_kernel<<<BT_ / 128, 256, G1_DYN>>>(xr, w_ih, b_ih, xpp);
    // Stage C: GRU recurrence + q
    gru_kernel<<<B_, 224>>>(xpp, w_hh, b_hh, w_reg, b_reg, qq);
    // Stage D: sitp windows + heads
    sitp_kernel<<<B_, T_>>>(qq, x_len, nlm_w1, nlm_b1, nlm_w2, nlm_b2,
                            lm_w, lm_b, out);
}